// round 2
// baseline (speedup 1.0000x reference)
#include <cuda_runtime.h>
#include <math.h>
#include <stdint.h>

// Problem constants (fixed shapes per reference)
#define BB 32
#define PP 16384
#define TT 64
#define NC 64                 // pred chunks per batch
#define CP (PP / NC)          // 256 preds per chunk
#define NSUB 16               // pred sub-streams
#define NT 4                  // targets per thread
#define TPB 256               // threads per block = (TT/NT) * NSUB = 16*16
#define PPT (CP / NSUB)       // 16 preds per thread

// Scratch (no allocations allowed)
__device__ float g_part_iou[BB * NC * TT];
__device__ int   g_part_idx[BB * NC * TT];
__device__ float g_conf_part[BB * NC];
__device__ float g_per[BB];

__device__ __forceinline__ float softplus_f(float x) {
    return fmaxf(x, 0.0f) + log1pf(expf(-fabsf(x)));
}

// Kernel 1: per (batch, chunk): for all 64 targets find local (max iou, min idx)
// over this chunk's 256 preds; also partial sum of softplus(logit).
__global__ void __launch_bounds__(TPB, 4) iou_kernel(
    const float* __restrict__ preds, const float* __restrict__ targets)
{
    const int c = blockIdx.x;
    const int b = blockIdx.y;
    const int tid = threadIdx.x;
    const int tg  = tid >> 4;    // 0..15 -> targets tg*4 .. tg*4+3
    const int sub = tid & 15;    // 0..15 -> pred sub-stream

    // Stage this chunk's preds (256 rows x 5 floats = 5KB) into smem, coalesced.
    __shared__ float sp[CP * 5];
    {
        const float4* src = (const float4*)(preds + ((size_t)b * PP + (size_t)c * CP) * 5);
        float4* dst = (float4*)sp;
        #pragma unroll
        for (int i = tid; i < CP * 5 / 4; i += TPB) dst[i] = src[i];
    }

    // Load this thread's 4 targets into registers
    float gx1[NT], gy1[NT], gx2[NT], gy2[NT], ga[NT];
    const float* tb = targets + (size_t)b * TT * 4;
    #pragma unroll
    for (int k = 0; k < NT; k++) {
        int t = tg * NT + k;
        float x = __ldg(tb + t * 4 + 0);
        float y = __ldg(tb + t * 4 + 1);
        float w = __ldg(tb + t * 4 + 2);
        float h = __ldg(tb + t * 4 + 3);
        gx1[k] = x; gy1[k] = y; gx2[k] = x + w; gy2[k] = y + h; ga[k] = w * h;
    }

    float biou[NT];
    int   bidx[NT];
    #pragma unroll
    for (int k = 0; k < NT; k++) { biou[k] = -1.0f; bidx[k] = 0x7fffffff; }

    __syncthreads();  // stage visible

    const int pbase_idx = c * CP;

    #pragma unroll 4
    for (int i = 0; i < PPT; i++) {
        const int pl = sub + i * NSUB;              // local pred row in smem
        const float* pr = sp + pl * 5;
        float px1 = pr[0];
        float py1 = pr[1];
        float pw  = pr[2];
        float ph  = pr[3];
        float px2 = px1 + pw, py2 = py1 + ph, pa = pw * ph;
        const int p = pbase_idx + pl;               // global pred index
        #pragma unroll
        for (int k = 0; k < NT; k++) {
            float xa = fmaxf(gx1[k], px1);
            float xb = fminf(gx2[k], px2);
            float ya = fmaxf(gy1[k], py1);
            float yb = fminf(gy2[k], py2);
            float w  = fmaxf(xb - xa, 0.0f);
            float h  = fmaxf(yb - ya, 0.0f);
            float inter = w * h;
            float u = pa + ga[k] - inter;
            float iou = __fdividef(inter, fmaxf(u, 1e-12f));
            if (iou > biou[k]) { biou[k] = iou; bidx[k] = p; }
        }
    }

    // Reduce across the 16 sub-streams per target (tie-break: min idx on equal iou)
    __shared__ float s_iou[TT][NSUB + 1];
    __shared__ int   s_idx[TT][NSUB + 1];
    #pragma unroll
    for (int k = 0; k < NT; k++) {
        s_iou[tg * NT + k][sub] = biou[k];
        s_idx[tg * NT + k][sub] = bidx[k];
    }
    __syncthreads();
    if (tid < TT) {
        float bi = -1.0f; int bx = 0x7fffffff;
        #pragma unroll
        for (int s = 0; s < NSUB; s++) {
            float v = s_iou[tid][s]; int id = s_idx[tid][s];
            if (v > bi || (v == bi && id < bx)) { bi = v; bx = id; }
        }
        g_part_iou[(b * NC + c) * TT + tid] = bi;
        g_part_idx[(b * NC + c) * TT + tid] = bx;
    }

    // Conf partial: sum softplus(logit) over this chunk's 256 logits (from smem)
    float acc = 0.0f;
    for (int i = tid; i < CP; i += TPB) {
        acc += softplus_f(sp[i * 5 + 4]);
    }
    __shared__ float s_red[TPB];
    s_red[tid] = acc;
    __syncthreads();
    for (int s = TPB / 2; s > 0; s >>= 1) {
        if (tid < s) s_red[tid] += s_red[tid + s];
        __syncthreads();
    }
    if (tid == 0) g_conf_part[b * NC + c] = s_red[0];
}

// Kernel 2: one block per batch (64 threads = one per target).
__global__ void __launch_bounds__(TT) finalize_kernel(
    const float* __restrict__ preds, const float* __restrict__ targets)
{
    const int b = blockIdx.x;
    const int t = threadIdx.x;

    float bi = -1.0f; int bx = 0x7fffffff;
    for (int c = 0; c < NC; c++) {
        float v = g_part_iou[(b * NC + c) * TT + t];
        int  id = g_part_idx[(b * NC + c) * TT + t];
        if (v > bi || (v == bi && id < bx)) { bi = v; bx = id; }
    }
    int val = (bi > 0.5f) ? bx : 0x7fffffff;

    __shared__ int vals[TT];
    vals[t] = val;
    __syncthreads();
    bool dup = false;
    if (val != 0x7fffffff) {
        for (int j = 0; j < t; j++) dup |= (vals[j] == val);
    }
    if (dup) val = 0x7fffffff;
    __syncthreads();
    vals[t] = val;
    __syncthreads();

    int rank = 0;
    for (int j = 0; j < TT; j++) {
        int vj = vals[j];
        rank += (vj < val) || (vj == val && j < t);
    }
    __shared__ int sorted_[TT];
    sorted_[rank] = val;
    int n = __syncthreads_count(val != 0x7fffffff);

    float sq = 0.0f, corr = 0.0f;
    if (t < n) {
        int p = sorted_[t];
        const float* pp = preds + ((size_t)b * PP + p) * 5;
        const float* tg = targets + ((size_t)b * TT + t) * 4;
        #pragma unroll
        for (int k = 0; k < 4; k++) {
            float d = __ldg(pp + k) - __ldg(tg + k);
            sq += d * d;
        }
        corr = -__ldg(pp + 4);  // softplus(-l) - softplus(l) == -l
    }
    // sum chunk conf partials: 64 threads over 64 chunks
    float base = g_conf_part[b * NC + t];

    __shared__ float sr[TT], sr2[TT], sr3[TT];
    sr[t] = sq; sr2[t] = corr; sr3[t] = base;
    __syncthreads();
    for (int s = TT / 2; s > 0; s >>= 1) {
        if (t < s) { sr[t] += sr[t + s]; sr2[t] += sr2[t + s]; sr3[t] += sr3[t + s]; }
        __syncthreads();
    }
    if (t == 0) {
        float conf = (sr3[0] + sr2[0]) * (1.0f / (float)PP);
        float bbox = sr[0] / fmaxf((float)n * 4.0f, 1.0f);
        g_per[b] = (n > 0) ? (bbox + conf) : 0.0f;
    }
}

// Kernel 3: sum per-image losses / B
__global__ void sum_kernel(float* __restrict__ out)
{
    int t = threadIdx.x;  // 32 threads
    float v = g_per[t];
    #pragma unroll
    for (int o = 16; o > 0; o >>= 1) v += __shfl_down_sync(0xffffffffu, v, o);
    if (t == 0) out[0] = v * (1.0f / (float)BB);
}

extern "C" void kernel_launch(void* const* d_in, const int* in_sizes, int n_in,
                              void* d_out, int out_size)
{
    const float* preds   = (const float*)d_in[0];
    const float* targets = (const float*)d_in[1];
    float* out = (float*)d_out;

    iou_kernel<<<dim3(NC, BB), TPB>>>(preds, targets);
    finalize_kernel<<<BB, TT>>>(preds, targets);
    sum_kernel<<<1, 32>>>(out);
}

// round 3
// speedup vs baseline: 1.1128x; 1.1128x over previous
#include <cuda_runtime.h>
#include <math.h>
#include <stdint.h>

// Problem constants (fixed shapes per reference)
#define BB 32
#define PP 16384
#define TT 64
#define NC 64                 // pred chunks per batch
#define CP (PP / NC)          // 256 preds per chunk
#define NSUB 16               // pred sub-streams
#define NT 4                  // targets per thread
#define TPB 256               // threads per block = (TT/NT) * NSUB
#define PPT (CP / NSUB)       // 16 preds per thread

// Scratch (no allocations allowed). Zero-initialized at module load;
// sum_kernel re-zeroes g_best at the end of every launch so the graph
// replays deterministically.
__device__ unsigned long long g_best[BB * TT];   // (iou_bits<<32) | (~p)
__device__ float g_conf_part[BB * NC];
__device__ float g_per[BB];

__device__ __forceinline__ float softplus_f(float x) {
    return fmaxf(x, 0.0f) + log1pf(expf(-fabsf(x)));
}

// Kernel 1: per (batch, chunk): for all 64 targets, atomically merge the
// chunk-local (max iou, min idx) into g_best; also conf partial.
__global__ void __launch_bounds__(TPB, 4) iou_kernel(
    const float* __restrict__ preds, const float* __restrict__ targets)
{
    const int c = blockIdx.x;
    const int b = blockIdx.y;
    const int tid = threadIdx.x;
    const int tg  = tid >> 4;    // 0..15 -> targets tg*4 .. tg*4+3
    const int sub = tid & 15;    // 0..15 -> pred sub-stream

    __shared__ float  sraw[CP * 5];     // staged raw preds
    __shared__ float4 sbox[CP];         // (x1, y1, x2, y2)
    __shared__ float  sarea[CP];
    __shared__ float  s_red[TPB];

    // Stage this chunk's preds (256 x 5 floats = 5KB), coalesced float4.
    {
        const float4* src = (const float4*)(preds + ((size_t)b * PP + (size_t)c * CP) * 5);
        float4* dst = (float4*)sraw;
        #pragma unroll
        for (int i = tid; i < CP * 5 / 4; i += TPB) dst[i] = src[i];
    }

    // Load this thread's 4 targets into registers (overlaps with staging)
    float gx1[NT], gy1[NT], gx2[NT], gy2[NT], ga[NT];
    const float* tb = targets + (size_t)b * TT * 4;
    #pragma unroll
    for (int k = 0; k < NT; k++) {
        int t = tg * NT + k;
        float x = __ldg(tb + t * 4 + 0);
        float y = __ldg(tb + t * 4 + 1);
        float w = __ldg(tb + t * 4 + 2);
        float h = __ldg(tb + t * 4 + 3);
        gx1[k] = x; gy1[k] = y; gx2[k] = x + w; gy2[k] = y + h; ga[k] = w * h;
    }

    __syncthreads();

    // Transform pass: one thread per pred row -> SoA + derived values.
    // Also compute this thread's softplus conf contribution.
    float conf_acc;
    {
        int r = tid;  // CP == TPB
        float x = sraw[r * 5 + 0];
        float y = sraw[r * 5 + 1];
        float w = sraw[r * 5 + 2];
        float h = sraw[r * 5 + 3];
        float l = sraw[r * 5 + 4];
        sbox[r]  = make_float4(x, y, x + w, y + h);
        sarea[r] = w * h;
        conf_acc = softplus_f(l);
    }

    float biou[NT];
    int   bidx[NT];
    #pragma unroll
    for (int k = 0; k < NT; k++) { biou[k] = -1.0f; bidx[k] = 0x7fffffff; }

    __syncthreads();

    const int pbase_idx = c * CP;

    #pragma unroll 4
    for (int i = 0; i < PPT; i++) {
        const int pl = sub + i * NSUB;
        float4 pb = sbox[pl];
        float  pa = sarea[pl];
        const int p = pbase_idx + pl;
        #pragma unroll
        for (int k = 0; k < NT; k++) {
            float xa = fmaxf(gx1[k], pb.x);
            float xb = fminf(gx2[k], pb.z);
            float ya = fmaxf(gy1[k], pb.y);
            float yb = fminf(gy2[k], pb.w);
            float w  = fmaxf(xb - xa, 0.0f);
            float h  = fmaxf(yb - ya, 0.0f);
            float inter = w * h;
            float u = pa + ga[k] - inter;
            float iou = __fdividef(inter, fmaxf(u, 1e-12f));
            if (iou > biou[k]) { biou[k] = iou; bidx[k] = p; }
        }
    }

    // Reduce across the 16 sub-streams per target (tie-break: min idx)
    __shared__ float s_iou[TT][NSUB + 1];
    __shared__ int   s_idx[TT][NSUB + 1];
    #pragma unroll
    for (int k = 0; k < NT; k++) {
        s_iou[tg * NT + k][sub] = biou[k];
        s_idx[tg * NT + k][sub] = bidx[k];
    }
    __syncthreads();
    if (tid < TT) {
        float bi = -1.0f; int bx = 0x7fffffff;
        #pragma unroll
        for (int s = 0; s < NSUB; s++) {
            float v = s_iou[tid][s]; int id = s_idx[tid][s];
            if (v > bi || (v == bi && id < bx)) { bi = v; bx = id; }
        }
        // iou >= 0 always, so float bits are order-preserving as u32.
        // (~p) in low word: equal iou -> larger key == smaller index.
        unsigned long long key =
            ((unsigned long long)__float_as_uint(bi) << 32) |
            (unsigned long long)(0xffffffffu - (unsigned)bx);
        atomicMax(&g_best[b * TT + tid], key);
    }

    // Conf partial reduce
    s_red[tid] = conf_acc;
    __syncthreads();
    for (int s = TPB / 2; s > 0; s >>= 1) {
        if (tid < s) s_red[tid] += s_red[tid + s];
        __syncthreads();
    }
    if (tid == 0) g_conf_part[b * NC + c] = s_red[0];
}

// Kernel 2: one block per batch (64 threads = one per target).
__global__ void __launch_bounds__(TT) finalize_kernel(
    const float* __restrict__ preds, const float* __restrict__ targets)
{
    const int b = blockIdx.x;
    const int t = threadIdx.x;

    unsigned long long key = g_best[b * TT + t];
    float bi = __uint_as_float((unsigned)(key >> 32));
    int   bx = (int)(0xffffffffu - (unsigned)key);
    int val = (bi > 0.5f) ? bx : 0x7fffffff;

    __shared__ int vals[TT];
    vals[t] = val;
    __syncthreads();
    bool dup = false;
    if (val != 0x7fffffff) {
        for (int j = 0; j < t; j++) dup |= (vals[j] == val);
    }
    if (dup) val = 0x7fffffff;
    __syncthreads();
    vals[t] = val;
    __syncthreads();

    int rank = 0;
    for (int j = 0; j < TT; j++) {
        int vj = vals[j];
        rank += (vj < val) || (vj == val && j < t);
    }
    __shared__ int sorted_[TT];
    sorted_[rank] = val;
    int n = __syncthreads_count(val != 0x7fffffff);

    float sq = 0.0f, corr = 0.0f;
    if (t < n) {
        int p = sorted_[t];
        const float* pp = preds + ((size_t)b * PP + p) * 5;
        const float* tg = targets + ((size_t)b * TT + t) * 4;
        #pragma unroll
        for (int k = 0; k < 4; k++) {
            float d = __ldg(pp + k) - __ldg(tg + k);
            sq += d * d;
        }
        corr = -__ldg(pp + 4);  // softplus(-l) - softplus(l) == -l
    }
    float base = g_conf_part[b * NC + t];  // NC == TT == 64

    __shared__ float sr[TT], sr2[TT], sr3[TT];
    sr[t] = sq; sr2[t] = corr; sr3[t] = base;
    __syncthreads();
    for (int s = TT / 2; s > 0; s >>= 1) {
        if (t < s) { sr[t] += sr[t + s]; sr2[t] += sr2[t + s]; sr3[t] += sr3[t + s]; }
        __syncthreads();
    }
    if (t == 0) {
        float conf = (sr3[0] + sr2[0]) * (1.0f / (float)PP);
        float bbox = sr[0] / fmaxf((float)n * 4.0f, 1.0f);
        g_per[b] = (n > 0) ? (bbox + conf) : 0.0f;
    }
}

// Kernel 3: sum per-image losses / B, then re-zero g_best for the next replay.
__global__ void sum_kernel(float* __restrict__ out)
{
    int t = threadIdx.x;  // 32 threads
    float v = g_per[t];
    #pragma unroll
    for (int o = 16; o > 0; o >>= 1) v += __shfl_down_sync(0xffffffffu, v, o);
    if (t == 0) out[0] = v * (1.0f / (float)BB);

    // reset the atomic accumulator for the next graph replay
    for (int i = t; i < BB * TT; i += 32) g_best[i] = 0ull;
}

extern "C" void kernel_launch(void* const* d_in, const int* in_sizes, int n_in,
                              void* d_out, int out_size)
{
    const float* preds   = (const float*)d_in[0];
    const float* targets = (const float*)d_in[1];
    float* out = (float*)d_out;

    iou_kernel<<<dim3(NC, BB), TPB>>>(preds, targets);
    finalize_kernel<<<BB, TT>>>(preds, targets);
    sum_kernel<<<1, 32>>>(out);
}